// round 4
// baseline (speedup 1.0000x reference)
#include <cuda_runtime.h>
#include <math.h>

#define NB   16
#define NL   1024
#define ND   512
#define NDH  64
#define KTOP 13

typedef unsigned long long ull;

// Scratch (no allocations allowed): 4 x 4MB fp32
__device__ float g_qp[NB * NDH * NL];   // q projection, [b][d][l]
__device__ float g_kp[NB * NDH * NL];   // k projection, [b][d][l]
__device__ float g_vp[NB * NDH * NL];   // v projection, [b][d][l]
__device__ float g_agg[NB * NDH * NL];  // aggregated result, [b][d][l]

// ---- f32x2 helpers --------------------------------------------------------
__device__ __forceinline__ ull pack2(float lo, float hi) {
    ull r; asm("mov.b64 %0, {%1, %2};" : "=l"(r) : "f"(lo), "f"(hi)); return r;
}
__device__ __forceinline__ void unpack2(ull v, float& lo, float& hi) {
    asm("mov.b64 {%0, %1}, %2;" : "=f"(lo), "=f"(hi) : "l"(v));
}
__device__ __forceinline__ void ffma2(ull& acc, ull a, ull b) {
    asm("fma.rn.f32x2 %0, %1, %2, %0;" : "+l"(acc) : "l"(a), "l"(b));
}

// ---- tf32 helpers ---------------------------------------------------------
__device__ __forceinline__ float tf32_rnd(float x) {
    unsigned u; asm("cvt.rna.tf32.f32 %0, %1;" : "=r"(u) : "f"(x));
    return __uint_as_float(u);
}
__device__ __forceinline__ void mma_tf32(float* c,
    float a0, float a1, float a2, float a3, float b0, float b1)
{
    asm volatile(
        "mma.sync.aligned.m16n8k8.row.col.f32.tf32.tf32.f32 "
        "{%0,%1,%2,%3}, {%4,%5,%6,%7}, {%8,%9}, {%0,%1,%2,%3};\n"
        : "+f"(c[0]), "+f"(c[1]), "+f"(c[2]), "+f"(c[3])
        : "r"(__float_as_uint(a0)), "r"(__float_as_uint(a1)),
          "r"(__float_as_uint(a2)), "r"(__float_as_uint(a3)),
          "r"(__float_as_uint(b0)), "r"(__float_as_uint(b1)));
}

// logical within-chunk k index -> physical f2 column (pairs (c,c+4)->(2c,2c+1))
__device__ __forceinline__ int kphys(int kk) {
    int w = kk & 7;
    return (kk >> 3) * 8 + ((w < 4) ? 2 * w : 2 * w - 7);
}

// ---------------------------------------------------------------------------
// Kernel 1: projection via tensor cores (3xTF32: big/small split, 3 MMAs).
// C[d=64][l=128] = W^T x^T per CTA. BK=16, 32 chunks, register prefetch.
// smem holds (big,small) float2 per element, k-permuted so every fragment
// load is one conflict-free LDS.128 (row stride 12 float4).
// grid (NL/128, NB, 3 matrices), 256 threads (8 warps of 32x32 C-tiles).
// ---------------------------------------------------------------------------
__global__ __launch_bounds__(256) void proj_kernel(
    const float* __restrict__ Q, const float* __restrict__ K,
    const float* __restrict__ V, const float* __restrict__ Wq,
    const float* __restrict__ bq)
{
    __shared__ __align__(16) float4 As4[NDH][12];   // W^T tile: [d][k f4]
    __shared__ __align__(16) float4 Bs4[128][12];   // x tile:   [l][k f4]
    float2* As2 = reinterpret_cast<float2*>(As4);   // row stride 24 f2
    float2* Bs2 = reinterpret_cast<float2*>(Bs4);

    const int b   = blockIdx.y;
    const int l0  = blockIdx.x * 128;
    const int mat = blockIdx.z;
    const int tid = threadIdx.x;
    const int wid  = tid >> 5;
    const int lane = tid & 31;
    const int g    = lane >> 2;        // groupID
    const int c    = lane & 3;         // threadID_in_group
    const int wm   = wid >> 2;         // 0..1 -> d-half
    const int wn   = wid & 3;          // 0..3 -> l-quarter

    const float* src = (mat == 0 ? Q : (mat == 1 ? K : V))
                     + ((size_t)b * NL + l0) * ND;
    float* dst = (mat == 0 ? g_qp : (mat == 1 ? g_kp : g_vp))
               + (size_t)b * NDH * NL + l0;

    // staging maps
    const int xl  = tid >> 2;          // x: row l (and +64), f4 col
    const int xk4 = (tid & 3) * 4;
    const int wkr = tid >> 4;          // W: k row within chunk
    const int wd4 = (tid & 15) * 4;

    float acc[2][4][4];
    #pragma unroll
    for (int i = 0; i < 2; ++i)
        #pragma unroll
        for (int j = 0; j < 4; ++j)
            #pragma unroll
            for (int r = 0; r < 4; ++r) acc[i][j][r] = 0.f;

    float4 xR0, xR1, wR;
    // prologue: chunk 0
    xR0 = *reinterpret_cast<const float4*>(src + (size_t)xl * ND + xk4);
    xR1 = *reinterpret_cast<const float4*>(src + (size_t)(xl + 64) * ND + xk4);
    wR  = *reinterpret_cast<const float4*>(Wq + (size_t)wkr * NDH + wd4);

    for (int ch = 0; ch < 32; ++ch) {
        // stage x (big,small) with k-permutation
        {
            const float xv0[4] = { xR0.x, xR0.y, xR0.z, xR0.w };
            const float xv1[4] = { xR1.x, xR1.y, xR1.z, xR1.w };
            #pragma unroll
            for (int j = 0; j < 4; ++j) {
                int pc = kphys(xk4 + j);
                float bgs = tf32_rnd(xv0[j]);
                Bs2[xl * 24 + pc]        = make_float2(bgs, tf32_rnd(xv0[j] - bgs));
                float bgs1 = tf32_rnd(xv1[j]);
                Bs2[(xl + 64) * 24 + pc] = make_float2(bgs1, tf32_rnd(xv1[j] - bgs1));
            }
            // stage W^T
            const float wv[4] = { wR.x, wR.y, wR.z, wR.w };
            int pc = kphys(wkr);
            #pragma unroll
            for (int j = 0; j < 4; ++j) {
                float bgs = tf32_rnd(wv[j]);
                As2[(wd4 + j) * 24 + pc] = make_float2(bgs, tf32_rnd(wv[j] - bgs));
            }
        }
        __syncthreads();

        // prefetch chunk ch+1
        if (ch < 31) {
            const int ko = (ch + 1) * 16;
            xR0 = *reinterpret_cast<const float4*>(src + (size_t)xl * ND + ko + xk4);
            xR1 = *reinterpret_cast<const float4*>(src + (size_t)(xl + 64) * ND + ko + xk4);
            wR  = *reinterpret_cast<const float4*>(Wq + (size_t)(ko + wkr) * NDH + wd4);
        }

        // compute: 2 k8-steps
        #pragma unroll
        for (int s = 0; s < 2; ++s) {
            float4 alo[2], ahi[2];
            #pragma unroll
            for (int mt = 0; mt < 2; ++mt) {
                int m = wm * 32 + mt * 16;
                alo[mt] = As4[m + g][s * 4 + c];       // a0b,a0s,a2b,a2s
                ahi[mt] = As4[m + 8 + g][s * 4 + c];   // a1b,a1s,a3b,a3s
            }
            #pragma unroll
            for (int nt = 0; nt < 4; ++nt) {
                int n = wn * 32 + nt * 8 + g;
                float4 bf = Bs4[n][s * 4 + c];         // b0b,b0s,b1b,b1s
                #pragma unroll
                for (int mt = 0; mt < 2; ++mt) {
                    mma_tf32(acc[mt][nt], alo[mt].x, ahi[mt].x, alo[mt].z, ahi[mt].z,
                             bf.x, bf.z);              // big x big
                    mma_tf32(acc[mt][nt], alo[mt].y, ahi[mt].y, alo[mt].w, ahi[mt].w,
                             bf.x, bf.z);              // small_A x big_B
                    mma_tf32(acc[mt][nt], alo[mt].x, ahi[mt].x, alo[mt].z, ahi[mt].z,
                             bf.y, bf.w);              // big_A x small_B
                }
            }
        }
        __syncthreads();
    }

    // epilogue: bias + transposed coalesced STG.64 (c0,c1 adjacent in l)
    #pragma unroll
    for (int mt = 0; mt < 2; ++mt) {
        int d0 = wm * 32 + mt * 16 + g;
        float bLo = bq[d0];
        float bHi = bq[d0 + 8];
        #pragma unroll
        for (int nt = 0; nt < 4; ++nt) {
            int l = wn * 32 + nt * 8 + 2 * c;
            float2 r0 = make_float2(acc[mt][nt][0] + bLo, acc[mt][nt][1] + bLo);
            float2 r1 = make_float2(acc[mt][nt][2] + bHi, acc[mt][nt][3] + bHi);
            *reinterpret_cast<float2*>(dst + (size_t)d0 * NL + l)       = r0;
            *reinterpret_cast<float2*>(dst + (size_t)(d0 + 8) * NL + l) = r1;
        }
    }
}

// ---------------------------------------------------------------------------
// Kernel 2: per-(b,d) series. r[tau] = sum_n q[n]*k[(n-tau) & 1023]
// == real(ifft(fft(q)*conj(fft(k)))). Then top-13 (ties -> lowest index),
// softmax, weighted circular gather of v. (unchanged from R3)
// ---------------------------------------------------------------------------
#define KP16(i) ((i) + 2 * ((i) >> 4))

__global__ __launch_bounds__(64) void corr_kernel()
{
    __shared__ __align__(16) float sq[NL];
    __shared__ __align__(16) float skp[2304];   // 2048 dup + 2-per-16 pad
    __shared__ __align__(16) float sv[NL];
    __shared__ float sc[NL];
    __shared__ float s_tv[KTOP];
    __shared__ int   s_ti[KTOP];
    __shared__ float s_w[KTOP];
    __shared__ float red_v[2];
    __shared__ int   red_i[2];

    const int b   = blockIdx.y;
    const int d   = blockIdx.x;
    const int tid = threadIdx.x;
    const size_t rowoff = ((size_t)b * NDH + d) * NL;
    const float* qrow = g_qp + rowoff;
    const float* krow = g_kp + rowoff;
    const float* vrow = g_vp + rowoff;

    #pragma unroll
    for (int j = 0; j < 16; ++j) {
        int i = tid + j * 64;
        sq[i] = qrow[i];
        sv[i] = vrow[i];
    }
    #pragma unroll
    for (int j = 0; j < 32; ++j) {
        int i = tid + j * 64;          // 0..2047
        skp[KP16(i)] = krow[i & 1023];
    }
    __syncthreads();

    const int t16 = tid * 16;
    const int m0  = 1024 - t16;        // m0 % 16 == 0, m0 >= 16
    const int pb0 = KP16(m0);

    ull E1 = *reinterpret_cast<const ull*>(&skp[pb0 -  4]);
    ull E2 = *reinterpret_cast<const ull*>(&skp[pb0 -  6]);
    ull E3 = *reinterpret_cast<const ull*>(&skp[pb0 -  8]);
    ull E4 = *reinterpret_cast<const ull*>(&skp[pb0 - 10]);
    ull E5 = *reinterpret_cast<const ull*>(&skp[pb0 - 12]);
    ull E6 = *reinterpret_cast<const ull*>(&skp[pb0 - 14]);
    ull E7 = *reinterpret_cast<const ull*>(&skp[pb0 - 16]);
    ull E8 = *reinterpret_cast<const ull*>(&skp[pb0 - 18]);
    float tl, th, tl2, th2;
    unpack2(E1, tl, th);
    float prev_hi = th;
    ull O1, O2, O3, O4, O5, O6, O7;
    unpack2(E2, tl2, th2); O1 = pack2(th2, tl);
    unpack2(E3, tl,  th ); O2 = pack2(th,  tl2);
    unpack2(E4, tl2, th2); O3 = pack2(th2, tl);
    unpack2(E5, tl,  th ); O4 = pack2(th,  tl2);
    unpack2(E6, tl2, th2); O5 = pack2(th2, tl);
    unpack2(E7, tl,  th ); O6 = pack2(th,  tl2);
    unpack2(E8, tl2, th2); O7 = pack2(th2, tl);

    ull ae0=0,ae1=0,ae2=0,ae3=0,ae4=0,ae5=0,ae6=0,ae7=0;
    ull ao0=0,ao1=0,ao2=0,ao3=0,ao4=0,ao5=0,ao6=0,ao7=0;

    int pb = pb0;
    for (int n0 = 0; n0 < NL; n0 += 16) {
        #pragma unroll
        for (int j = 0; j < 8; ++j) {
            ull E0 = *reinterpret_cast<const ull*>(&skp[pb + 2 * j]);
            float lo0, hi0; unpack2(E0, lo0, hi0);
            ull O0 = pack2(prev_hi, lo0);
            ull q2 = *reinterpret_cast<const ull*>(&sq[n0 + 2 * j]);
            ffma2(ae0, q2, E0); ffma2(ao0, q2, O0);
            ffma2(ae1, q2, E1); ffma2(ao1, q2, O1);
            ffma2(ae2, q2, E2); ffma2(ao2, q2, O2);
            ffma2(ae3, q2, E3); ffma2(ao3, q2, O3);
            ffma2(ae4, q2, E4); ffma2(ao4, q2, O4);
            ffma2(ae5, q2, E5); ffma2(ao5, q2, O5);
            ffma2(ae6, q2, E6); ffma2(ao6, q2, O6);
            ffma2(ae7, q2, E7); ffma2(ao7, q2, O7);
            E7 = E6; E6 = E5; E5 = E4; E4 = E3; E3 = E2; E2 = E1; E1 = E0;
            O7 = O6; O6 = O5; O5 = O4; O4 = O3; O3 = O2; O2 = O1; O1 = O0;
            prev_hi = hi0;
        }
        pb += 18;                       // 16 elements + 2 pad, linear
    }

    {
        float lo, hi;
        unpack2(ae0, lo, hi); sc[t16 +  0] = lo + hi;
        unpack2(ao0, lo, hi); sc[t16 +  1] = lo + hi;
        unpack2(ae1, lo, hi); sc[t16 +  2] = lo + hi;
        unpack2(ao1, lo, hi); sc[t16 +  3] = lo + hi;
        unpack2(ae2, lo, hi); sc[t16 +  4] = lo + hi;
        unpack2(ao2, lo, hi); sc[t16 +  5] = lo + hi;
        unpack2(ae3, lo, hi); sc[t16 +  6] = lo + hi;
        unpack2(ao3, lo, hi); sc[t16 +  7] = lo + hi;
        unpack2(ae4, lo, hi); sc[t16 +  8] = lo + hi;
        unpack2(ao4, lo, hi); sc[t16 +  9] = lo + hi;
        unpack2(ae5, lo, hi); sc[t16 + 10] = lo + hi;
        unpack2(ao5, lo, hi); sc[t16 + 11] = lo + hi;
        unpack2(ae6, lo, hi); sc[t16 + 12] = lo + hi;
        unpack2(ao6, lo, hi); sc[t16 + 13] = lo + hi;
        unpack2(ae7, lo, hi); sc[t16 + 14] = lo + hi;
        unpack2(ao7, lo, hi); sc[t16 + 15] = lo + hi;
    }
    __syncthreads();

    for (int k = 0; k < KTOP; ++k) {
        float bv = -3.0e38f; int bi = 1 << 30;
        #pragma unroll
        for (int j = 0; j < 16; ++j) {
            int   idx = t16 + j;
            float v   = sc[idx];
            if (v > bv) { bv = v; bi = idx; }
        }
        #pragma unroll
        for (int off = 16; off > 0; off >>= 1) {
            float ov = __shfl_down_sync(0xffffffffu, bv, off);
            int   oi = __shfl_down_sync(0xffffffffu, bi, off);
            if (ov > bv || (ov == bv && oi < bi)) { bv = ov; bi = oi; }
        }
        if ((tid & 31) == 0) { red_v[tid >> 5] = bv; red_i[tid >> 5] = bi; }
        __syncthreads();
        if (tid == 0) {
            bv = red_v[0]; bi = red_i[0];
            if (red_v[1] > bv || (red_v[1] == bv && red_i[1] < bi)) {
                bv = red_v[1]; bi = red_i[1];
            }
            s_tv[k] = bv; s_ti[k] = bi;
            sc[bi]  = -3.4e38f;
        }
        __syncthreads();
    }

    if (tid == 0) {
        float mx = s_tv[0];
        float e[KTOP], sum = 0.f;
        #pragma unroll
        for (int k = 0; k < KTOP; ++k) { e[k] = expf(s_tv[k] - mx); sum += e[k]; }
        float inv = 1.0f / sum;
        #pragma unroll
        for (int k = 0; k < KTOP; ++k) s_w[k] = e[k] * inv;
    }
    __syncthreads();

    float* aggrow = g_agg + rowoff;
    #pragma unroll
    for (int j = 0; j < 16; ++j) {
        int l = tid + j * 64;
        float acc = 0.f;
        #pragma unroll
        for (int k = 0; k < KTOP; ++k)
            acc += s_w[k] * sv[(l + s_ti[k]) & 1023];
        aggrow[l] = acc;
    }
}

// ---------------------------------------------------------------------------
// Kernel 3: transpose-broadcast agg[b][d][l] -> out[b][l][h*64+d], h=0..7
// ---------------------------------------------------------------------------
__global__ __launch_bounds__(256) void out_kernel(float* __restrict__ out)
{
    __shared__ float t[64][33];
    const int b   = blockIdx.y;
    const int l0  = blockIdx.x * 32;
    const int tid = threadIdx.x;
    const float* agg = g_agg + (size_t)b * NDH * NL;

    #pragma unroll
    for (int i = 0; i < 8; ++i) {
        int flat = tid + i * 256;   // 2048 = 64 d x 32 l
        int dd   = flat >> 5;
        int ll   = flat & 31;
        t[dd][ll] = agg[(size_t)dd * NL + l0 + ll];
    }
    __syncthreads();

    float* obase = out + ((size_t)b * NL + l0) * (NDH * 8);
    #pragma unroll
    for (int i = 0; i < 16; ++i) {
        int f4  = tid + i * 256;    // 4096 float4 = 32 l x 128 ch4
        int ll  = f4 >> 7;
        int c0  = (f4 & 127) * 4;
        int cc  = c0 & 63;
        float4 v = make_float4(t[cc][ll], t[cc + 1][ll], t[cc + 2][ll], t[cc + 3][ll]);
        *reinterpret_cast<float4*>(obase + (size_t)ll * 512 + c0) = v;
    }
}

// ---------------------------------------------------------------------------
extern "C" void kernel_launch(void* const* d_in, const int* in_sizes, int n_in,
                              void* d_out, int out_size)
{
    const float* Q  = (const float*)d_in[0];
    const float* K  = (const float*)d_in[1];
    const float* V  = (const float*)d_in[2];
    const float* Wq = (const float*)d_in[3];
    const float* bq = (const float*)d_in[4];
    float* out = (float*)d_out;

    proj_kernel<<<dim3(NL / 128, NB, 3), 256>>>(Q, K, V, Wq, bq);
    corr_kernel<<<dim3(NDH, NB), 64>>>();
    out_kernel<<<dim3(NL / 32, NB), 256>>>(out);
}

// round 5
// speedup vs baseline: 1.8167x; 1.8167x over previous
#include <cuda_runtime.h>
#include <math.h>

#define NB   16
#define NL   1024
#define ND   512
#define NDH  64
#define KTOP 13

typedef unsigned long long ull;

// Scratch (no allocations allowed): 4 x 4MB fp32
__device__ float g_qp[NB * NDH * NL];   // q projection, [b][d][l]
__device__ float g_kp[NB * NDH * NL];   // k projection, [b][d][l]
__device__ float g_vp[NB * NDH * NL];   // v projection, [b][d][l]
__device__ float g_agg[NB * NDH * NL];  // aggregated result, [b][d][l]

// ---- f32x2 helpers --------------------------------------------------------
__device__ __forceinline__ ull pack2(float lo, float hi) {
    ull r; asm("mov.b64 %0, {%1, %2};" : "=l"(r) : "f"(lo), "f"(hi)); return r;
}
__device__ __forceinline__ void unpack2(ull v, float& lo, float& hi) {
    asm("mov.b64 {%0, %1}, %2;" : "=f"(lo), "=f"(hi) : "l"(v));
}
__device__ __forceinline__ void ffma2(ull& acc, ull a, ull b) {
    asm("fma.rn.f32x2 %0, %1, %2, %0;" : "+l"(acc) : "l"(a), "l"(b));
}

// ---- bf16 split helpers (truncation split: err ~2^-16 relative) -----------
// x -> (hi,hi) word and (lo,lo) word (for B planes)
__device__ __forceinline__ void split_dup(float x, unsigned& wh, unsigned& wl) {
    unsigned u = __float_as_uint(x);
    float hi = __uint_as_float(u & 0xFFFF0000u);
    unsigned lu = __float_as_uint(x - hi);
    wh = __byte_perm(u,  u,  0x3232);
    wl = __byte_perm(lu, lu, 0x3232);
}
// x -> (hi, lo) interleaved word (for A)
__device__ __forceinline__ unsigned split_pack(float x) {
    unsigned u = __float_as_uint(x);
    float hi = __uint_as_float(u & 0xFFFF0000u);
    unsigned lu = __float_as_uint(x - hi);
    return __byte_perm(u, lu, 0x7632);
}

__device__ __forceinline__ void mma_bf16(float* c, const unsigned* a,
                                         unsigned b0, unsigned b1) {
    asm volatile(
        "mma.sync.aligned.m16n8k16.row.col.f32.bf16.bf16.f32 "
        "{%0,%1,%2,%3}, {%4,%5,%6,%7}, {%8,%9}, {%0,%1,%2,%3};\n"
        : "+f"(c[0]), "+f"(c[1]), "+f"(c[2]), "+f"(c[3])
        : "r"(a[0]), "r"(a[1]), "r"(a[2]), "r"(a[3]), "r"(b0), "r"(b1));
}

// swizzled smem word index: 32 words per row; group (w>>3) XOR'd by row&3,
// half-of-group flipped by row>>2&1.  Conflict-free for both the STS.128
// staging pattern and the LDS.32 fragment pattern.
__device__ __forceinline__ int smidx(int row, int w) {
    return row * 32 + (((w >> 3) ^ (row & 3)) << 3)
         + ((w & 7) ^ (((row >> 2) & 1) << 2));
}

// ---------------------------------------------------------------------------
// Kernel 1: projection x @ Wq + bq -> [b][d][l], via bf16 tensor cores with
// split-K doubling (2 MMAs per k16-step reproduce full fp32-ish product).
// CTA: C[d=64][l=128], K=512 real -> 16 chunks of 32. 256 thr, 8 warps of
// 32(d) x 32(l) tiles. Single-buffered smem + register prefetch.
// ---------------------------------------------------------------------------
__global__ __launch_bounds__(256) void proj_kernel(
    const float* __restrict__ Q, const float* __restrict__ K,
    const float* __restrict__ V, const float* __restrict__ Wq,
    const float* __restrict__ bq)
{
    __shared__ unsigned Ws[64 * 32];    // A tile: (hiW,loW) interleaved words
    __shared__ unsigned Xh[128 * 32];   // B plane: (hiX,hiX) words
    __shared__ unsigned Xl[128 * 32];   // B plane: (loX,loX) words

    const int b    = blockIdx.y;
    const int l0   = blockIdx.x * 128;
    const int mat  = blockIdx.z;
    const int tid  = threadIdx.x;
    const int wid  = tid >> 5;
    const int lane = tid & 31;
    const int g    = lane >> 2;
    const int cq   = lane & 3;
    const int wm   = wid >> 2;          // 0..1 -> d half
    const int wn   = wid & 3;           // 0..3 -> l quarter
    const int m_base = wm * 32;
    const int n_base = wn * 32;

    const float* src = (mat == 0 ? Q : (mat == 1 ? K : V))
                     + ((size_t)b * NL + l0) * ND;
    float* dst = (mat == 0 ? g_qp : (mat == 1 ? g_kp : g_vp))
               + (size_t)b * NDH * NL + l0;

    // ---- staging maps (constant over chunks) ----
    // x: 1024 float4 per chunk -> 4 per thread
    int xrow[4], xgb[4], xsb[4];
    #pragma unroll
    for (int i = 0; i < 4; ++i) {
        int f4id = tid + i * 256;
        int r    = f4id >> 3;
        int c4   = f4id & 7;
        xrow[i]  = r;
        xgb[i]   = r * ND + c4 * 4;
        xsb[i]   = r * 32 + (((c4 >> 1) ^ (r & 3)) << 3)
                 + (((c4 & 1) << 2) ^ (((r >> 2) & 1) << 2));
    }
    // W: 512 quads (d, 4 consecutive k) per chunk -> 2 per thread
    int wdd[2], wkq[2], wsb[2];
    #pragma unroll
    for (int i = 0; i < 2; ++i) {
        int qid = tid + i * 256;
        wdd[i]  = qid & 63;
        wkq[i]  = qid >> 6;             // 0..7
        wsb[i]  = wdd[i] * 32 + (((wkq[i] >> 1) ^ (wdd[i] & 3)) << 3)
                + (((wkq[i] & 1) << 2) ^ (((wdd[i] >> 2) & 1) << 2));
    }

    float acc[2][4][4];
    #pragma unroll
    for (int mt = 0; mt < 2; ++mt)
        #pragma unroll
        for (int nt = 0; nt < 4; ++nt)
            #pragma unroll
            for (int r = 0; r < 4; ++r) acc[mt][nt][r] = 0.f;

    // prologue LDG chunk 0
    float4 xR[4];
    float  wF[8];
    #pragma unroll
    for (int i = 0; i < 4; ++i)
        xR[i] = *reinterpret_cast<const float4*>(src + xgb[i]);
    #pragma unroll
    for (int i = 0; i < 2; ++i)
        #pragma unroll
        for (int j = 0; j < 4; ++j)
            wF[i * 4 + j] = Wq[(size_t)(wkq[i] * 4 + j) * NDH + wdd[i]];

    for (int ch = 0; ch < 16; ++ch) {
        // ---- stage chunk ch ----
        #pragma unroll
        for (int i = 0; i < 4; ++i) {
            unsigned h0,h1,h2,h3, q0,q1,q2,q3;
            split_dup(xR[i].x, h0, q0);
            split_dup(xR[i].y, h1, q1);
            split_dup(xR[i].z, h2, q2);
            split_dup(xR[i].w, h3, q3);
            *reinterpret_cast<uint4*>(&Xh[xsb[i]]) = make_uint4(h0,h1,h2,h3);
            *reinterpret_cast<uint4*>(&Xl[xsb[i]]) = make_uint4(q0,q1,q2,q3);
        }
        #pragma unroll
        for (int i = 0; i < 2; ++i) {
            unsigned w0 = split_pack(wF[i * 4 + 0]);
            unsigned w1 = split_pack(wF[i * 4 + 1]);
            unsigned w2 = split_pack(wF[i * 4 + 2]);
            unsigned w3 = split_pack(wF[i * 4 + 3]);
            *reinterpret_cast<uint4*>(&Ws[wsb[i]]) = make_uint4(w0,w1,w2,w3);
        }
        __syncthreads();

        // ---- prefetch chunk ch+1 ----
        if (ch < 15) {
            const int ko = (ch + 1) * 32;
            #pragma unroll
            for (int i = 0; i < 4; ++i)
                xR[i] = *reinterpret_cast<const float4*>(src + xgb[i] + ko);
            #pragma unroll
            for (int i = 0; i < 2; ++i)
                #pragma unroll
                for (int j = 0; j < 4; ++j)
                    wF[i * 4 + j] = Wq[(size_t)(ko + wkq[i] * 4 + j) * NDH + wdd[i]];
        }

        // ---- compute chunk ch: 4 k16-steps x 2 planes ----
        #pragma unroll
        for (int ks = 0; ks < 4; ++ks) {
            unsigned a[2][4];
            #pragma unroll
            for (int mt = 0; mt < 2; ++mt) {
                int r0 = m_base + mt * 16 + g;
                int r1 = r0 + 8;
                a[mt][0] = Ws[smidx(r0, ks * 8 + cq)];
                a[mt][1] = Ws[smidx(r1, ks * 8 + cq)];
                a[mt][2] = Ws[smidx(r0, ks * 8 + cq + 4)];
                a[mt][3] = Ws[smidx(r1, ks * 8 + cq + 4)];
            }
            #pragma unroll
            for (int nt = 0; nt < 4; ++nt) {
                int rn = n_base + nt * 8 + g;
                unsigned bh0 = Xh[smidx(rn, ks * 8 + cq)];
                unsigned bh1 = Xh[smidx(rn, ks * 8 + cq + 4)];
                unsigned bl0 = Xl[smidx(rn, ks * 8 + cq)];
                unsigned bl1 = Xl[smidx(rn, ks * 8 + cq + 4)];
                #pragma unroll
                for (int mt = 0; mt < 2; ++mt) {
                    mma_bf16(acc[mt][nt], a[mt], bh0, bh1);   // hh + lh
                    mma_bf16(acc[mt][nt], a[mt], bl0, bl1);   // hl + ll
                }
            }
        }
        __syncthreads();
    }

    // ---- epilogue: bias + transposed coalesced STG.64 ----
    #pragma unroll
    for (int mt = 0; mt < 2; ++mt) {
        int d0 = m_base + mt * 16 + g;
        float bLo = bq[d0];
        float bHi = bq[d0 + 8];
        #pragma unroll
        for (int nt = 0; nt < 4; ++nt) {
            int l = n_base + nt * 8 + 2 * cq;
            float2 r0 = make_float2(acc[mt][nt][0] + bLo, acc[mt][nt][1] + bLo);
            float2 r1 = make_float2(acc[mt][nt][2] + bHi, acc[mt][nt][3] + bHi);
            *reinterpret_cast<float2*>(dst + (size_t)d0 * NL + l)       = r0;
            *reinterpret_cast<float2*>(dst + (size_t)(d0 + 8) * NL + l) = r1;
        }
    }
}

// ---------------------------------------------------------------------------
// Kernel 2: per-(b,d) series. r[tau] = sum_n q[n]*k[(n-tau) & 1023]
// == real(ifft(fft(q)*conj(fft(k)))). Then top-13 (ties -> lowest index),
// softmax, weighted circular gather of v. (unchanged from R3)
// ---------------------------------------------------------------------------
#define KP16(i) ((i) + 2 * ((i) >> 4))

__global__ __launch_bounds__(64) void corr_kernel()
{
    __shared__ __align__(16) float sq[NL];
    __shared__ __align__(16) float skp[2304];   // 2048 dup + 2-per-16 pad
    __shared__ __align__(16) float sv[NL];
    __shared__ float sc[NL];
    __shared__ float s_tv[KTOP];
    __shared__ int   s_ti[KTOP];
    __shared__ float s_w[KTOP];
    __shared__ float red_v[2];
    __shared__ int   red_i[2];

    const int b   = blockIdx.y;
    const int d   = blockIdx.x;
    const int tid = threadIdx.x;
    const size_t rowoff = ((size_t)b * NDH + d) * NL;
    const float* qrow = g_qp + rowoff;
    const float* krow = g_kp + rowoff;
    const float* vrow = g_vp + rowoff;

    #pragma unroll
    for (int j = 0; j < 16; ++j) {
        int i = tid + j * 64;
        sq[i] = qrow[i];
        sv[i] = vrow[i];
    }
    #pragma unroll
    for (int j = 0; j < 32; ++j) {
        int i = tid + j * 64;          // 0..2047
        skp[KP16(i)] = krow[i & 1023];
    }
    __syncthreads();

    const int t16 = tid * 16;
    const int m0  = 1024 - t16;        // m0 % 16 == 0, m0 >= 16
    const int pb0 = KP16(m0);

    ull E1 = *reinterpret_cast<const ull*>(&skp[pb0 -  4]);
    ull E2 = *reinterpret_cast<const ull*>(&skp[pb0 -  6]);
    ull E3 = *reinterpret_cast<const ull*>(&skp[pb0 -  8]);
    ull E4 = *reinterpret_cast<const ull*>(&skp[pb0 - 10]);
    ull E5 = *reinterpret_cast<const ull*>(&skp[pb0 - 12]);
    ull E6 = *reinterpret_cast<const ull*>(&skp[pb0 - 14]);
    ull E7 = *reinterpret_cast<const ull*>(&skp[pb0 - 16]);
    ull E8 = *reinterpret_cast<const ull*>(&skp[pb0 - 18]);
    float tl, th, tl2, th2;
    unpack2(E1, tl, th);
    float prev_hi = th;
    ull O1, O2, O3, O4, O5, O6, O7;
    unpack2(E2, tl2, th2); O1 = pack2(th2, tl);
    unpack2(E3, tl,  th ); O2 = pack2(th,  tl2);
    unpack2(E4, tl2, th2); O3 = pack2(th2, tl);
    unpack2(E5, tl,  th ); O4 = pack2(th,  tl2);
    unpack2(E6, tl2, th2); O5 = pack2(th2, tl);
    unpack2(E7, tl,  th ); O6 = pack2(th,  tl2);
    unpack2(E8, tl2, th2); O7 = pack2(th2, tl);

    ull ae0=0,ae1=0,ae2=0,ae3=0,ae4=0,ae5=0,ae6=0,ae7=0;
    ull ao0=0,ao1=0,ao2=0,ao3=0,ao4=0,ao5=0,ao6=0,ao7=0;

    int pb = pb0;
    for (int n0 = 0; n0 < NL; n0 += 16) {
        #pragma unroll
        for (int j = 0; j < 8; ++j) {
            ull E0 = *reinterpret_cast<const ull*>(&skp[pb + 2 * j]);
            float lo0, hi0; unpack2(E0, lo0, hi0);
            ull O0 = pack2(prev_hi, lo0);
            ull q2 = *reinterpret_cast<const ull*>(&sq[n0 + 2 * j]);
            ffma2(ae0, q2, E0); ffma2(ao0, q2, O0);
            ffma2(ae1, q2, E1); ffma2(ao1, q2, O1);
            ffma2(ae2, q2, E2); ffma2(ao2, q2, O2);
            ffma2(ae3, q2, E3); ffma2(ao3, q2, O3);
            ffma2(ae4, q2, E4); ffma2(ao4, q2, O4);
            ffma2(ae5, q2, E5); ffma2(ao5, q2, O5);
            ffma2(ae6, q2, E6); ffma2(ao6, q2, O6);
            ffma2(ae7, q2, E7); ffma2(ao7, q2, O7);
            E7 = E6; E6 = E5; E5 = E4; E4 = E3; E3 = E2; E2 = E1; E1 = E0;
            O7 = O6; O6 = O5; O5 = O4; O4 = O3; O3 = O2; O2 = O1; O1 = O0;
            prev_hi = hi0;
        }
        pb += 18;                       // 16 elements + 2 pad, linear
    }

    {
        float lo, hi;
        unpack2(ae0, lo, hi); sc[t16 +  0] = lo + hi;
        unpack2(ao0, lo, hi); sc[t16 +  1] = lo + hi;
        unpack2(ae1, lo, hi); sc[t16 +  2] = lo + hi;
        unpack2(ao1, lo, hi); sc[t16 +  3] = lo + hi;
        unpack2(ae2, lo, hi); sc[t16 +  4] = lo + hi;
        unpack2(ao2, lo, hi); sc[t16 +  5] = lo + hi;
        unpack2(ae3, lo, hi); sc[t16 +  6] = lo + hi;
        unpack2(ao3, lo, hi); sc[t16 +  7] = lo + hi;
        unpack2(ae4, lo, hi); sc[t16 +  8] = lo + hi;
        unpack2(ao4, lo, hi); sc[t16 +  9] = lo + hi;
        unpack2(ae5, lo, hi); sc[t16 + 10] = lo + hi;
        unpack2(ao5, lo, hi); sc[t16 + 11] = lo + hi;
        unpack2(ae6, lo, hi); sc[t16 + 12] = lo + hi;
        unpack2(ao6, lo, hi); sc[t16 + 13] = lo + hi;
        unpack2(ae7, lo, hi); sc[t16 + 14] = lo + hi;
        unpack2(ao7, lo, hi); sc[t16 + 15] = lo + hi;
    }
    __syncthreads();

    for (int k = 0; k < KTOP; ++k) {
        float bv = -3.0e38f; int bi = 1 << 30;
        #pragma unroll
        for (int j = 0; j < 16; ++j) {
            int   idx = t16 + j;
            float v   = sc[idx];
            if (v > bv) { bv = v; bi = idx; }
        }
        #pragma unroll
        for (int off = 16; off > 0; off >>= 1) {
            float ov = __shfl_down_sync(0xffffffffu, bv, off);
            int   oi = __shfl_down_sync(0xffffffffu, bi, off);
            if (ov > bv || (ov == bv && oi < bi)) { bv = ov; bi = oi; }
        }
        if ((tid & 31) == 0) { red_v[tid >> 5] = bv; red_i[tid >> 5] = bi; }
        __syncthreads();
        if (tid == 0) {
            bv = red_v[0]; bi = red_i[0];
            if (red_v[1] > bv || (red_v[1] == bv && red_i[1] < bi)) {
                bv = red_v[1]; bi = red_i[1];
            }
            s_tv[k] = bv; s_ti[k] = bi;
            sc[bi]  = -3.4e38f;
        }
        __syncthreads();
    }

    if (tid == 0) {
        float mx = s_tv[0];
        float e[KTOP], sum = 0.f;
        #pragma unroll
        for (int k = 0; k < KTOP; ++k) { e[k] = expf(s_tv[k] - mx); sum += e[k]; }
        float inv = 1.0f / sum;
        #pragma unroll
        for (int k = 0; k < KTOP; ++k) s_w[k] = e[k] * inv;
    }
    __syncthreads();

    float* aggrow = g_agg + rowoff;
    #pragma unroll
    for (int j = 0; j < 16; ++j) {
        int l = tid + j * 64;
        float acc = 0.f;
        #pragma unroll
        for (int k = 0; k < KTOP; ++k)
            acc += s_w[k] * sv[(l + s_ti[k]) & 1023];
        aggrow[l] = acc;
    }
}

// ---------------------------------------------------------------------------
// Kernel 3: transpose-broadcast agg[b][d][l] -> out[b][l][h*64+d], h=0..7
// ---------------------------------------------------------------------------
__global__ __launch_bounds__(256) void out_kernel(float* __restrict__ out)
{
    __shared__ float t[64][33];
    const int b   = blockIdx.y;
    const int l0  = blockIdx.x * 32;
    const int tid = threadIdx.x;
    const float* agg = g_agg + (size_t)b * NDH * NL;

    #pragma unroll
    for (int i = 0; i < 8; ++i) {
        int flat = tid + i * 256;   // 2048 = 64 d x 32 l
        int dd   = flat >> 5;
        int ll   = flat & 31;
        t[dd][ll] = agg[(size_t)dd * NL + l0 + ll];
    }
    __syncthreads();

    float* obase = out + ((size_t)b * NL + l0) * (NDH * 8);
    #pragma unroll
    for (int i = 0; i < 16; ++i) {
        int f4  = tid + i * 256;    // 4096 float4 = 32 l x 128 ch4
        int ll  = f4 >> 7;
        int c0  = (f4 & 127) * 4;
        int cc  = c0 & 63;
        float4 v = make_float4(t[cc][ll], t[cc + 1][ll], t[cc + 2][ll], t[cc + 3][ll]);
        *reinterpret_cast<float4*>(obase + (size_t)ll * 512 + c0) = v;
    }
}

// ---------------------------------------------------------------------------
extern "C" void kernel_launch(void* const* d_in, const int* in_sizes, int n_in,
                              void* d_out, int out_size)
{
    const float* Q  = (const float*)d_in[0];
    const float* K  = (const float*)d_in[1];
    const float* V  = (const float*)d_in[2];
    const float* Wq = (const float*)d_in[3];
    const float* bq = (const float*)d_in[4];
    float* out = (float*)d_out;

    proj_kernel<<<dim3(NL / 128, NB, 3), 256>>>(Q, K, V, Wq, bq);
    corr_kernel<<<dim3(NDH, NB), 64>>>();
    out_kernel<<<dim3(NL / 32, NB), 256>>>(out);
}

// round 6
// speedup vs baseline: 1.8392x; 1.0124x over previous
#include <cuda_runtime.h>
#include <math.h>

#define NB   16
#define NL   1024
#define ND   512
#define NDH  64
#define KTOP 13

typedef unsigned long long ull;

// Scratch (no allocations allowed): 4 x 4MB fp32
__device__ float g_qp[NB * NDH * NL];   // q projection, [b][d][l]
__device__ float g_kp[NB * NDH * NL];   // k projection, [b][d][l]
__device__ float g_vp[NB * NDH * NL];   // v projection, [b][d][l]
__device__ float g_agg[NB * NDH * NL];  // aggregated result, [b][d][l]

// ---- f32x2 helpers --------------------------------------------------------
__device__ __forceinline__ ull pack2(float lo, float hi) {
    ull r; asm("mov.b64 %0, {%1, %2};" : "=l"(r) : "f"(lo), "f"(hi)); return r;
}
__device__ __forceinline__ void unpack2(ull v, float& lo, float& hi) {
    asm("mov.b64 {%0, %1}, %2;" : "=f"(lo), "=f"(hi) : "l"(v));
}
__device__ __forceinline__ void ffma2(ull& acc, ull a, ull b) {
    asm("fma.rn.f32x2 %0, %1, %2, %0;" : "+l"(acc) : "l"(a), "l"(b));
}

// ---- bf16 split helpers (truncation split: err ~2^-16 relative) -----------
// x -> (hi,hi) word and (lo,lo) word (for B planes)
__device__ __forceinline__ void split_dup(float x, unsigned& wh, unsigned& wl) {
    unsigned u = __float_as_uint(x);
    float hi = __uint_as_float(u & 0xFFFF0000u);
    unsigned lu = __float_as_uint(x - hi);
    wh = __byte_perm(u,  u,  0x3232);
    wl = __byte_perm(lu, lu, 0x3232);
}
// x -> (hi, lo) interleaved word (for A)
__device__ __forceinline__ unsigned split_pack(float x) {
    unsigned u = __float_as_uint(x);
    float hi = __uint_as_float(u & 0xFFFF0000u);
    unsigned lu = __float_as_uint(x - hi);
    return __byte_perm(u, lu, 0x7632);
}

__device__ __forceinline__ void mma_bf16(float* c, const unsigned* a,
                                         unsigned b0, unsigned b1) {
    asm volatile(
        "mma.sync.aligned.m16n8k16.row.col.f32.bf16.bf16.f32 "
        "{%0,%1,%2,%3}, {%4,%5,%6,%7}, {%8,%9}, {%0,%1,%2,%3};\n"
        : "+f"(c[0]), "+f"(c[1]), "+f"(c[2]), "+f"(c[3])
        : "r"(a[0]), "r"(a[1]), "r"(a[2]), "r"(a[3]), "r"(b0), "r"(b1));
}

// swizzled smem word index: 32 words per row; group (w>>3) XOR'd by row&3,
// half-of-group flipped by row>>2&1.  Conflict-free for both the STS.128
// staging pattern and the LDS.32 fragment pattern.
__device__ __forceinline__ int smidx(int row, int w) {
    return row * 32 + (((w >> 3) ^ (row & 3)) << 3)
         + ((w & 7) ^ (((row >> 2) & 1) << 2));
}

// ---------------------------------------------------------------------------
// Kernel 1: projection x @ Wq + bq -> [b][d][l], via bf16 tensor cores with
// split-K doubling (2 MMAs per k16-step reproduce full fp32-ish product).
// CTA: C[d=64][l=128], K=512 real -> 16 chunks of 32. 256 thr, 8 warps of
// 32(d) x 32(l) tiles. Single-buffered smem + register prefetch.
// ---------------------------------------------------------------------------
__global__ __launch_bounds__(256) void proj_kernel(
    const float* __restrict__ Q, const float* __restrict__ K,
    const float* __restrict__ V, const float* __restrict__ Wq,
    const float* __restrict__ bq)
{
    __shared__ unsigned Ws[64 * 32];    // A tile: (hiW,loW) interleaved words
    __shared__ unsigned Xh[128 * 32];   // B plane: (hiX,hiX) words
    __shared__ unsigned Xl[128 * 32];   // B plane: (loX,loX) words

    const int b    = blockIdx.y;
    const int l0   = blockIdx.x * 128;
    const int mat  = blockIdx.z;
    const int tid  = threadIdx.x;
    const int wid  = tid >> 5;
    const int lane = tid & 31;
    const int g    = lane >> 2;
    const int cq   = lane & 3;
    const int wm   = wid >> 2;          // 0..1 -> d half
    const int wn   = wid & 3;           // 0..3 -> l quarter
    const int m_base = wm * 32;
    const int n_base = wn * 32;

    const float* src = (mat == 0 ? Q : (mat == 1 ? K : V))
                     + ((size_t)b * NL + l0) * ND;
    float* dst = (mat == 0 ? g_qp : (mat == 1 ? g_kp : g_vp))
               + (size_t)b * NDH * NL + l0;

    // ---- staging maps (constant over chunks) ----
    // x: 1024 float4 per chunk -> 4 per thread
    int xrow[4], xgb[4], xsb[4];
    #pragma unroll
    for (int i = 0; i < 4; ++i) {
        int f4id = tid + i * 256;
        int r    = f4id >> 3;
        int c4   = f4id & 7;
        xrow[i]  = r;
        xgb[i]   = r * ND + c4 * 4;
        xsb[i]   = r * 32 + (((c4 >> 1) ^ (r & 3)) << 3)
                 + (((c4 & 1) << 2) ^ (((r >> 2) & 1) << 2));
    }
    // W: 512 quads (d, 4 consecutive k) per chunk -> 2 per thread
    int wdd[2], wkq[2], wsb[2];
    #pragma unroll
    for (int i = 0; i < 2; ++i) {
        int qid = tid + i * 256;
        wdd[i]  = qid & 63;
        wkq[i]  = qid >> 6;             // 0..7
        wsb[i]  = wdd[i] * 32 + (((wkq[i] >> 1) ^ (wdd[i] & 3)) << 3)
                + (((wkq[i] & 1) << 2) ^ (((wdd[i] >> 2) & 1) << 2));
    }

    float acc[2][4][4];
    #pragma unroll
    for (int mt = 0; mt < 2; ++mt)
        #pragma unroll
        for (int nt = 0; nt < 4; ++nt)
            #pragma unroll
            for (int r = 0; r < 4; ++r) acc[mt][nt][r] = 0.f;

    // prologue LDG chunk 0
    float4 xR[4];
    float  wF[8];
    #pragma unroll
    for (int i = 0; i < 4; ++i)
        xR[i] = *reinterpret_cast<const float4*>(src + xgb[i]);
    #pragma unroll
    for (int i = 0; i < 2; ++i)
        #pragma unroll
        for (int j = 0; j < 4; ++j)
            wF[i * 4 + j] = Wq[(size_t)(wkq[i] * 4 + j) * NDH + wdd[i]];

    for (int ch = 0; ch < 16; ++ch) {
        // ---- stage chunk ch ----
        #pragma unroll
        for (int i = 0; i < 4; ++i) {
            unsigned h0,h1,h2,h3, q0,q1,q2,q3;
            split_dup(xR[i].x, h0, q0);
            split_dup(xR[i].y, h1, q1);
            split_dup(xR[i].z, h2, q2);
            split_dup(xR[i].w, h3, q3);
            *reinterpret_cast<uint4*>(&Xh[xsb[i]]) = make_uint4(h0,h1,h2,h3);
            *reinterpret_cast<uint4*>(&Xl[xsb[i]]) = make_uint4(q0,q1,q2,q3);
        }
        #pragma unroll
        for (int i = 0; i < 2; ++i) {
            unsigned w0 = split_pack(wF[i * 4 + 0]);
            unsigned w1 = split_pack(wF[i * 4 + 1]);
            unsigned w2 = split_pack(wF[i * 4 + 2]);
            unsigned w3 = split_pack(wF[i * 4 + 3]);
            *reinterpret_cast<uint4*>(&Ws[wsb[i]]) = make_uint4(w0,w1,w2,w3);
        }
        __syncthreads();

        // ---- prefetch chunk ch+1 ----
        if (ch < 15) {
            const int ko = (ch + 1) * 32;
            #pragma unroll
            for (int i = 0; i < 4; ++i)
                xR[i] = *reinterpret_cast<const float4*>(src + xgb[i] + ko);
            #pragma unroll
            for (int i = 0; i < 2; ++i)
                #pragma unroll
                for (int j = 0; j < 4; ++j)
                    wF[i * 4 + j] = Wq[(size_t)(ko + wkq[i] * 4 + j) * NDH + wdd[i]];
        }

        // ---- compute chunk ch: 4 k16-steps x 2 planes ----
        #pragma unroll
        for (int ks = 0; ks < 4; ++ks) {
            unsigned a[2][4];
            #pragma unroll
            for (int mt = 0; mt < 2; ++mt) {
                int r0 = m_base + mt * 16 + g;
                int r1 = r0 + 8;
                a[mt][0] = Ws[smidx(r0, ks * 8 + cq)];
                a[mt][1] = Ws[smidx(r1, ks * 8 + cq)];
                a[mt][2] = Ws[smidx(r0, ks * 8 + cq + 4)];
                a[mt][3] = Ws[smidx(r1, ks * 8 + cq + 4)];
            }
            #pragma unroll
            for (int nt = 0; nt < 4; ++nt) {
                int rn = n_base + nt * 8 + g;
                unsigned bh0 = Xh[smidx(rn, ks * 8 + cq)];
                unsigned bh1 = Xh[smidx(rn, ks * 8 + cq + 4)];
                unsigned bl0 = Xl[smidx(rn, ks * 8 + cq)];
                unsigned bl1 = Xl[smidx(rn, ks * 8 + cq + 4)];
                #pragma unroll
                for (int mt = 0; mt < 2; ++mt) {
                    mma_bf16(acc[mt][nt], a[mt], bh0, bh1);   // hh + lh
                    mma_bf16(acc[mt][nt], a[mt], bl0, bl1);   // hl + ll
                }
            }
        }
        __syncthreads();
    }

    // ---- epilogue: bias + transposed coalesced STG.64 ----
    #pragma unroll
    for (int mt = 0; mt < 2; ++mt) {
        int d0 = m_base + mt * 16 + g;
        float bLo = bq[d0];
        float bHi = bq[d0 + 8];
        #pragma unroll
        for (int nt = 0; nt < 4; ++nt) {
            int l = n_base + nt * 8 + 2 * cq;
            float2 r0 = make_float2(acc[mt][nt][0] + bLo, acc[mt][nt][1] + bLo);
            float2 r1 = make_float2(acc[mt][nt][2] + bHi, acc[mt][nt][3] + bHi);
            *reinterpret_cast<float2*>(dst + (size_t)d0 * NL + l)       = r0;
            *reinterpret_cast<float2*>(dst + (size_t)(d0 + 8) * NL + l) = r1;
        }
    }
}

// ---------------------------------------------------------------------------
// Kernel 2: per-(b,d) series. r[tau] = sum_n q[n]*k[(n-tau) & 1023]
// == real(ifft(fft(q)*conj(fft(k)))). Then top-13 (ties -> lowest index),
// softmax, weighted circular gather of v. (unchanged from R3)
// ---------------------------------------------------------------------------
#define KP16(i) ((i) + 2 * ((i) >> 4))

__global__ __launch_bounds__(64) void corr_kernel()
{
    __shared__ __align__(16) float sq[NL];
    __shared__ __align__(16) float skp[2304];   // 2048 dup + 2-per-16 pad
    __shared__ __align__(16) float sv[NL];
    __shared__ float sc[NL];
    __shared__ float s_tv[KTOP];
    __shared__ int   s_ti[KTOP];
    __shared__ float s_w[KTOP];
    __shared__ float red_v[2];
    __shared__ int   red_i[2];

    const int b   = blockIdx.y;
    const int d   = blockIdx.x;
    const int tid = threadIdx.x;
    const size_t rowoff = ((size_t)b * NDH + d) * NL;
    const float* qrow = g_qp + rowoff;
    const float* krow = g_kp + rowoff;
    const float* vrow = g_vp + rowoff;

    #pragma unroll
    for (int j = 0; j < 16; ++j) {
        int i = tid + j * 64;
        sq[i] = qrow[i];
        sv[i] = vrow[i];
    }
    #pragma unroll
    for (int j = 0; j < 32; ++j) {
        int i = tid + j * 64;          // 0..2047
        skp[KP16(i)] = krow[i & 1023];
    }
    __syncthreads();

    const int t16 = tid * 16;
    const int m0  = 1024 - t16;        // m0 % 16 == 0, m0 >= 16
    const int pb0 = KP16(m0);

    ull E1 = *reinterpret_cast<const ull*>(&skp[pb0 -  4]);
    ull E2 = *reinterpret_cast<const ull*>(&skp[pb0 -  6]);
    ull E3 = *reinterpret_cast<const ull*>(&skp[pb0 -  8]);
    ull E4 = *reinterpret_cast<const ull*>(&skp[pb0 - 10]);
    ull E5 = *reinterpret_cast<const ull*>(&skp[pb0 - 12]);
    ull E6 = *reinterpret_cast<const ull*>(&skp[pb0 - 14]);
    ull E7 = *reinterpret_cast<const ull*>(&skp[pb0 - 16]);
    ull E8 = *reinterpret_cast<const ull*>(&skp[pb0 - 18]);
    float tl, th, tl2, th2;
    unpack2(E1, tl, th);
    float prev_hi = th;
    ull O1, O2, O3, O4, O5, O6, O7;
    unpack2(E2, tl2, th2); O1 = pack2(th2, tl);
    unpack2(E3, tl,  th ); O2 = pack2(th,  tl2);
    unpack2(E4, tl2, th2); O3 = pack2(th2, tl);
    unpack2(E5, tl,  th ); O4 = pack2(th,  tl2);
    unpack2(E6, tl2, th2); O5 = pack2(th2, tl);
    unpack2(E7, tl,  th ); O6 = pack2(th,  tl2);
    unpack2(E8, tl2, th2); O7 = pack2(th2, tl);

    ull ae0=0,ae1=0,ae2=0,ae3=0,ae4=0,ae5=0,ae6=0,ae7=0;
    ull ao0=0,ao1=0,ao2=0,ao3=0,ao4=0,ao5=0,ao6=0,ao7=0;

    int pb = pb0;
    for (int n0 = 0; n0 < NL; n0 += 16) {
        #pragma unroll
        for (int j = 0; j < 8; ++j) {
            ull E0 = *reinterpret_cast<const ull*>(&skp[pb + 2 * j]);
            float lo0, hi0; unpack2(E0, lo0, hi0);
            ull O0 = pack2(prev_hi, lo0);
            ull q2 = *reinterpret_cast<const ull*>(&sq[n0 + 2 * j]);
            ffma2(ae0, q2, E0); ffma2(ao0, q2, O0);
            ffma2(ae1, q2, E1); ffma2(ao1, q2, O1);
            ffma2(ae2, q2, E2); ffma2(ao2, q2, O2);
            ffma2(ae3, q2, E3); ffma2(ao3, q2, O3);
            ffma2(ae4, q2, E4); ffma2(ao4, q2, O4);
            ffma2(ae5, q2, E5); ffma2(ao5, q2, O5);
            ffma2(ae6, q2, E6); ffma2(ao6, q2, O6);
            ffma2(ae7, q2, E7); ffma2(ao7, q2, O7);
            E7 = E6; E6 = E5; E5 = E4; E4 = E3; E3 = E2; E2 = E1; E1 = E0;
            O7 = O6; O6 = O5; O5 = O4; O4 = O3; O3 = O2; O2 = O1; O1 = O0;
            prev_hi = hi0;
        }
        pb += 18;                       // 16 elements + 2 pad, linear
    }

    {
        float lo, hi;
        unpack2(ae0, lo, hi); sc[t16 +  0] = lo + hi;
        unpack2(ao0, lo, hi); sc[t16 +  1] = lo + hi;
        unpack2(ae1, lo, hi); sc[t16 +  2] = lo + hi;
        unpack2(ao1, lo, hi); sc[t16 +  3] = lo + hi;
        unpack2(ae2, lo, hi); sc[t16 +  4] = lo + hi;
        unpack2(ao2, lo, hi); sc[t16 +  5] = lo + hi;
        unpack2(ae3, lo, hi); sc[t16 +  6] = lo + hi;
        unpack2(ao3, lo, hi); sc[t16 +  7] = lo + hi;
        unpack2(ae4, lo, hi); sc[t16 +  8] = lo + hi;
        unpack2(ao4, lo, hi); sc[t16 +  9] = lo + hi;
        unpack2(ae5, lo, hi); sc[t16 + 10] = lo + hi;
        unpack2(ao5, lo, hi); sc[t16 + 11] = lo + hi;
        unpack2(ae6, lo, hi); sc[t16 + 12] = lo + hi;
        unpack2(ao6, lo, hi); sc[t16 + 13] = lo + hi;
        unpack2(ae7, lo, hi); sc[t16 + 14] = lo + hi;
        unpack2(ao7, lo, hi); sc[t16 + 15] = lo + hi;
    }
    __syncthreads();

    for (int k = 0; k < KTOP; ++k) {
        float bv = -3.0e38f; int bi = 1 << 30;
        #pragma unroll
        for (int j = 0; j < 16; ++j) {
            int   idx = t16 + j;
            float v   = sc[idx];
            if (v > bv) { bv = v; bi = idx; }
        }
        #pragma unroll
        for (int off = 16; off > 0; off >>= 1) {
            float ov = __shfl_down_sync(0xffffffffu, bv, off);
            int   oi = __shfl_down_sync(0xffffffffu, bi, off);
            if (ov > bv || (ov == bv && oi < bi)) { bv = ov; bi = oi; }
        }
        if ((tid & 31) == 0) { red_v[tid >> 5] = bv; red_i[tid >> 5] = bi; }
        __syncthreads();
        if (tid == 0) {
            bv = red_v[0]; bi = red_i[0];
            if (red_v[1] > bv || (red_v[1] == bv && red_i[1] < bi)) {
                bv = red_v[1]; bi = red_i[1];
            }
            s_tv[k] = bv; s_ti[k] = bi;
            sc[bi]  = -3.4e38f;
        }
        __syncthreads();
    }

    if (tid == 0) {
        float mx = s_tv[0];
        float e[KTOP], sum = 0.f;
        #pragma unroll
        for (int k = 0; k < KTOP; ++k) { e[k] = expf(s_tv[k] - mx); sum += e[k]; }
        float inv = 1.0f / sum;
        #pragma unroll
        for (int k = 0; k < KTOP; ++k) s_w[k] = e[k] * inv;
    }
    __syncthreads();

    float* aggrow = g_agg + rowoff;
    #pragma unroll
    for (int j = 0; j < 16; ++j) {
        int l = tid + j * 64;
        float acc = 0.f;
        #pragma unroll
        for (int k = 0; k < KTOP; ++k)
            acc += s_w[k] * sv[(l + s_ti[k]) & 1023];
        aggrow[l] = acc;
    }
}

// ---------------------------------------------------------------------------
// Kernel 3: transpose-broadcast agg[b][d][l] -> out[b][l][h*64+d], h=0..7
// ---------------------------------------------------------------------------
__global__ __launch_bounds__(256) void out_kernel(float* __restrict__ out)
{
    __shared__ float t[64][33];
    const int b   = blockIdx.y;
    const int l0  = blockIdx.x * 32;
    const int tid = threadIdx.x;
    const float* agg = g_agg + (size_t)b * NDH * NL;

    #pragma unroll
    for (int i = 0; i < 8; ++i) {
        int flat = tid + i * 256;   // 2048 = 64 d x 32 l
        int dd   = flat >> 5;
        int ll   = flat & 31;
        t[dd][ll] = agg[(size_t)dd * NL + l0 + ll];
    }
    __syncthreads();

    float* obase = out + ((size_t)b * NL + l0) * (NDH * 8);
    #pragma unroll
    for (int i = 0; i < 16; ++i) {
        int f4  = tid + i * 256;    // 4096 float4 = 32 l x 128 ch4
        int ll  = f4 >> 7;
        int c0  = (f4 & 127) * 4;
        int cc  = c0 & 63;
        float4 v = make_float4(t[cc][ll], t[cc + 1][ll], t[cc + 2][ll], t[cc + 3][ll]);
        *reinterpret_cast<float4*>(obase + (size_t)ll * 512 + c0) = v;
    }
}

// ---------------------------------------------------------------------------
extern "C" void kernel_launch(void* const* d_in, const int* in_sizes, int n_in,
                              void* d_out, int out_size)
{
    const float* Q  = (const float*)d_in[0];
    const float* K  = (const float*)d_in[1];
    const float* V  = (const float*)d_in[2];
    const float* Wq = (const float*)d_in[3];
    const float* bq = (const float*)d_in[4];
    float* out = (float*)d_out;

    proj_kernel<<<dim3(NL / 128, NB, 3), 256>>>(Q, K, V, Wq, bq);
    corr_kernel<<<dim3(NDH, NB), 64>>>();
    out_kernel<<<dim3(NL / 32, NB), 256>>>(out);
}

// round 7
// speedup vs baseline: 2.5475x; 1.3851x over previous
#include <cuda_runtime.h>
#include <math.h>

#define NB   16
#define NL   1024
#define ND   512
#define NDH  64
#define KTOP 13

// Scratch (no allocations allowed): 4 x 4MB fp32
__device__ float g_qp[NB * NDH * NL];   // q projection, [b][d][l]
__device__ float g_kp[NB * NDH * NL];   // k projection, [b][d][l]
__device__ float g_vp[NB * NDH * NL];   // v projection, [b][d][l]
__device__ float g_agg[NB * NDH * NL];  // aggregated result, [b][d][l]

// ---- bf16 split helpers (truncation split) --------------------------------
__device__ __forceinline__ void split_dup(float x, unsigned& wh, unsigned& wl) {
    unsigned u = __float_as_uint(x);
    float hi = __uint_as_float(u & 0xFFFF0000u);
    unsigned lu = __float_as_uint(x - hi);
    wh = __byte_perm(u,  u,  0x3232);
    wl = __byte_perm(lu, lu, 0x3232);
}
__device__ __forceinline__ unsigned split_pack(float x) {
    unsigned u = __float_as_uint(x);
    float hi = __uint_as_float(u & 0xFFFF0000u);
    unsigned lu = __float_as_uint(x - hi);
    return __byte_perm(u, lu, 0x7632);
}

__device__ __forceinline__ void mma_bf16(float* c, const unsigned* a,
                                         unsigned b0, unsigned b1) {
    asm volatile(
        "mma.sync.aligned.m16n8k16.row.col.f32.bf16.bf16.f32 "
        "{%0,%1,%2,%3}, {%4,%5,%6,%7}, {%8,%9}, {%0,%1,%2,%3};\n"
        : "+f"(c[0]), "+f"(c[1]), "+f"(c[2]), "+f"(c[3])
        : "r"(a[0]), "r"(a[1]), "r"(a[2]), "r"(a[3]), "r"(b0), "r"(b1));
}

__device__ __forceinline__ int smidx(int row, int w) {
    return row * 32 + (((w >> 3) ^ (row & 3)) << 3)
         + ((w & 7) ^ (((row >> 2) & 1) << 2));
}

// ---------------------------------------------------------------------------
// Kernel 1: projection via bf16 tensor cores, split-K doubling (unchanged).
// ---------------------------------------------------------------------------
__global__ __launch_bounds__(256) void proj_kernel(
    const float* __restrict__ Q, const float* __restrict__ K,
    const float* __restrict__ V, const float* __restrict__ Wq,
    const float* __restrict__ bq)
{
    __shared__ unsigned Ws[64 * 32];
    __shared__ unsigned Xh[128 * 32];
    __shared__ unsigned Xl[128 * 32];

    const int b    = blockIdx.y;
    const int l0   = blockIdx.x * 128;
    const int mat  = blockIdx.z;
    const int tid  = threadIdx.x;
    const int wid  = tid >> 5;
    const int lane = tid & 31;
    const int g    = lane >> 2;
    const int cq   = lane & 3;
    const int m_base = (wid >> 2) * 32;
    const int n_base = (wid & 3) * 32;

    const float* src = (mat == 0 ? Q : (mat == 1 ? K : V))
                     + ((size_t)b * NL + l0) * ND;
    float* dst = (mat == 0 ? g_qp : (mat == 1 ? g_kp : g_vp))
               + (size_t)b * NDH * NL + l0;

    int xgb[4], xsb[4];
    #pragma unroll
    for (int i = 0; i < 4; ++i) {
        int f4id = tid + i * 256;
        int r    = f4id >> 3;
        int c4   = f4id & 7;
        xgb[i]   = r * ND + c4 * 4;
        xsb[i]   = r * 32 + (((c4 >> 1) ^ (r & 3)) << 3)
                 + (((c4 & 1) << 2) ^ (((r >> 2) & 1) << 2));
    }
    int wdd[2], wkq[2], wsb[2];
    #pragma unroll
    for (int i = 0; i < 2; ++i) {
        int qid = tid + i * 256;
        wdd[i]  = qid & 63;
        wkq[i]  = qid >> 6;
        wsb[i]  = wdd[i] * 32 + (((wkq[i] >> 1) ^ (wdd[i] & 3)) << 3)
                + (((wkq[i] & 1) << 2) ^ (((wdd[i] >> 2) & 1) << 2));
    }

    float acc[2][4][4];
    #pragma unroll
    for (int mt = 0; mt < 2; ++mt)
        #pragma unroll
        for (int nt = 0; nt < 4; ++nt)
            #pragma unroll
            for (int r = 0; r < 4; ++r) acc[mt][nt][r] = 0.f;

    float4 xR[4];
    float  wF[8];
    #pragma unroll
    for (int i = 0; i < 4; ++i)
        xR[i] = *reinterpret_cast<const float4*>(src + xgb[i]);
    #pragma unroll
    for (int i = 0; i < 2; ++i)
        #pragma unroll
        for (int j = 0; j < 4; ++j)
            wF[i * 4 + j] = Wq[(size_t)(wkq[i] * 4 + j) * NDH + wdd[i]];

    for (int ch = 0; ch < 16; ++ch) {
        #pragma unroll
        for (int i = 0; i < 4; ++i) {
            unsigned h0,h1,h2,h3, q0,q1,q2,q3;
            split_dup(xR[i].x, h0, q0);
            split_dup(xR[i].y, h1, q1);
            split_dup(xR[i].z, h2, q2);
            split_dup(xR[i].w, h3, q3);
            *reinterpret_cast<uint4*>(&Xh[xsb[i]]) = make_uint4(h0,h1,h2,h3);
            *reinterpret_cast<uint4*>(&Xl[xsb[i]]) = make_uint4(q0,q1,q2,q3);
        }
        #pragma unroll
        for (int i = 0; i < 2; ++i) {
            *reinterpret_cast<uint4*>(&Ws[wsb[i]]) = make_uint4(
                split_pack(wF[i*4+0]), split_pack(wF[i*4+1]),
                split_pack(wF[i*4+2]), split_pack(wF[i*4+3]));
        }
        __syncthreads();

        if (ch < 15) {
            const int ko = (ch + 1) * 32;
            #pragma unroll
            for (int i = 0; i < 4; ++i)
                xR[i] = *reinterpret_cast<const float4*>(src + xgb[i] + ko);
            #pragma unroll
            for (int i = 0; i < 2; ++i)
                #pragma unroll
                for (int j = 0; j < 4; ++j)
                    wF[i * 4 + j] = Wq[(size_t)(ko + wkq[i] * 4 + j) * NDH + wdd[i]];
        }

        #pragma unroll
        for (int ks = 0; ks < 4; ++ks) {
            unsigned a[2][4];
            #pragma unroll
            for (int mt = 0; mt < 2; ++mt) {
                int r0 = m_base + mt * 16 + g;
                a[mt][0] = Ws[smidx(r0,     ks * 8 + cq)];
                a[mt][1] = Ws[smidx(r0 + 8, ks * 8 + cq)];
                a[mt][2] = Ws[smidx(r0,     ks * 8 + cq + 4)];
                a[mt][3] = Ws[smidx(r0 + 8, ks * 8 + cq + 4)];
            }
            #pragma unroll
            for (int nt = 0; nt < 4; ++nt) {
                int rn = n_base + nt * 8 + g;
                unsigned bh0 = Xh[smidx(rn, ks * 8 + cq)];
                unsigned bh1 = Xh[smidx(rn, ks * 8 + cq + 4)];
                unsigned bl0 = Xl[smidx(rn, ks * 8 + cq)];
                unsigned bl1 = Xl[smidx(rn, ks * 8 + cq + 4)];
                #pragma unroll
                for (int mt = 0; mt < 2; ++mt) {
                    mma_bf16(acc[mt][nt], a[mt], bh0, bh1);
                    mma_bf16(acc[mt][nt], a[mt], bl0, bl1);
                }
            }
        }
        __syncthreads();
    }

    #pragma unroll
    for (int mt = 0; mt < 2; ++mt) {
        int d0 = m_base + mt * 16 + g;
        float bLo = bq[d0];
        float bHi = bq[d0 + 8];
        #pragma unroll
        for (int nt = 0; nt < 4; ++nt) {
            int l = n_base + nt * 8 + 2 * cq;
            float2 r0 = make_float2(acc[mt][nt][0] + bLo, acc[mt][nt][1] + bLo);
            float2 r1 = make_float2(acc[mt][nt][2] + bHi, acc[mt][nt][3] + bHi);
            *reinterpret_cast<float2*>(dst + (size_t)d0 * NL + l)       = r0;
            *reinterpret_cast<float2*>(dst + (size_t)(d0 + 8) * NL + l) = r1;
        }
    }
}

// ---------------------------------------------------------------------------
// Kernel 2 (NEW): corr via FFT, exactly the reference algorithm:
//   corr = real(ifft(fft(q) * conj(fft(k))))
// Two series (d0, d0+1) per CTA, 128 threads.
//  fwd: z = q + i*k, one Stockham radix-2 1024-pt FFT (both series at once)
//  Q[f]=(Z[f]+conj(Z[-f]))/2 ; K[f]=(Z[f]-conj(Z[-f]))/(2i) ; S=Q*conj(K)
//  inv: T = S_a + i*S_b ; ifft(T) = conj(FFT(conj T))/N -> (corr_a, corr_b)
// Then top-13 (ties -> lowest index), softmax, weighted circular v-gather.
// Stockham stage (s=2^st): a=src[i], b=src[i+512], j=i&~(s-1):
//   dst[i+j]=a+b ; dst[i+j+s]=tw[j]*(a-b),  tw[j]=exp(-2*pi*i*j/1024).
// ---------------------------------------------------------------------------
__global__ __launch_bounds__(128) void corr_kernel()
{
    __shared__ __align__(16) float2 fbuf[4096];   // 32 KB workspace
    __shared__ float2 tw[512];
    __shared__ float s_tv[2][KTOP];
    __shared__ int   s_ti[2][KTOP];
    __shared__ float s_w[2][KTOP];
    __shared__ float red_v[4];
    __shared__ int   red_i[4];

    const int b   = blockIdx.y;
    const int d0  = blockIdx.x * 2;
    const int tid = threadIdx.x;
    float* fbf = reinterpret_cast<float*>(fbuf);
    const size_t offA = ((size_t)b * NDH + d0) * NL;

    for (int j = tid; j < 512; j += 128) {
        float s, c;
        sincospif(-(float)j / 512.0f, &s, &c);
        tw[j] = make_float2(c, s);
    }
    // load z = q + i*k for both series (rows are contiguous)
    {
        const float4* qa = reinterpret_cast<const float4*>(g_qp + offA);
        const float4* ka = reinterpret_cast<const float4*>(g_kp + offA);
        for (int i = tid; i < 512; i += 128) {
            float4 q = qa[i], k = ka[i];
            int o = i * 4;
            fbuf[o+0] = make_float2(q.x, k.x);
            fbuf[o+1] = make_float2(q.y, k.y);
            fbuf[o+2] = make_float2(q.z, k.z);
            fbuf[o+3] = make_float2(q.w, k.w);
        }
    }
    __syncthreads();

    // forward FFT, both series at once (series offset 'so'), ping-pong 0<->2048
    int src = 0;
    for (int st = 0; st < 10; ++st) {
        const int s = 1 << st;
        const int dst = src ^ 2048;
        #pragma unroll 2
        for (int it = 0; it < 8; ++it) {
            int t  = tid + it * 128;
            int so = (t >> 9) << 10;
            int u  = t & 511;
            int j  = u & ~(s - 1);
            float2 a  = fbuf[src + so + u];
            float2 bb = fbuf[src + so + u + 512];
            float2 w  = tw[j];
            float2 df = make_float2(a.x - bb.x, a.y - bb.y);
            fbuf[dst + so + u + j]     = make_float2(a.x + bb.x, a.y + bb.y);
            fbuf[dst + so + u + j + s] = make_float2(w.x*df.x - w.y*df.y,
                                                     w.x*df.y + w.y*df.x);
        }
        __syncthreads();
        src = dst;
    }
    // result in [0,2048)

    // spectral: S = Q * conj(K); T = S_a + i*S_b; store conj(T) in [2048,3072)
    for (int it = 0; it < 8; ++it) {
        int f  = tid + it * 128;
        int fn = (1024 - f) & 1023;
        float2 Za = fbuf[f],        Zan = fbuf[fn];
        float2 Zb = fbuf[1024 + f], Zbn = fbuf[1024 + fn];
        float qx = 0.5f*(Za.x + Zan.x), qy = 0.5f*(Za.y - Zan.y);
        float kx = 0.5f*(Za.y + Zan.y), ky = -0.5f*(Za.x - Zan.x);
        float sax = qx*kx + qy*ky, say = qy*kx - qx*ky;
        float qx2 = 0.5f*(Zb.x + Zbn.x), qy2 = 0.5f*(Zb.y - Zbn.y);
        float kx2 = 0.5f*(Zb.y + Zbn.y), ky2 = -0.5f*(Zb.x - Zbn.x);
        float sbx = qx2*kx2 + qy2*ky2, sby = qy2*kx2 - qx2*ky2;
        fbuf[2048 + f] = make_float2(sax - sby, -(say + sbx));
    }
    __syncthreads();

    // load v for both series into floats [6144,8192) — untouched by inverse
    {
        const float4* va = reinterpret_cast<const float4*>(g_vp + offA);
        for (int i = tid; i < 512; i += 128)
            *reinterpret_cast<float4*>(&fbf[6144 + i * 4]) = va[i];
    }

    // inverse FFT (forward FFT of conj T), ping-pong [2048,3072) <-> [0,1024)
    int s2 = 2048;
    for (int st = 0; st < 10; ++st) {
        const int s = 1 << st;
        const int dst = (s2 == 2048) ? 0 : 2048;
        #pragma unroll 2
        for (int it = 0; it < 4; ++it) {
            int u = tid + it * 128;
            int j = u & ~(s - 1);
            float2 a  = fbuf[s2 + u];
            float2 bb = fbuf[s2 + u + 512];
            float2 w  = tw[j];
            float2 df = make_float2(a.x - bb.x, a.y - bb.y);
            fbuf[dst + u + j]     = make_float2(a.x + bb.x, a.y + bb.y);
            fbuf[dst + u + j + s] = make_float2(w.x*df.x - w.y*df.y,
                                                w.x*df.y + w.y*df.x);
        }
        __syncthreads();
        s2 = dst;
    }
    // result in [2048,3072): ifft = conj(F)/N -> corr_a = Re/N, corr_b = -Im/N

    const float invN = 1.0f / 1024.0f;
    for (int it = 0; it < 8; ++it) {
        int n = tid + it * 128;
        float2 F = fbuf[2048 + n];
        fbf[n]        =  F.x * invN;
        fbf[1024 + n] = -F.y * invN;
    }
    __syncthreads();

    // top-13 per series: warps 0-1 -> series A, warps 2-3 -> series B
    const int sid = tid >> 6;
    const int lt  = tid & 63;
    float* sc = fbf + (sid << 10);
    const int base = lt * 16;
    for (int p = 0; p < KTOP; ++p) {
        float bv = -3.0e38f; int bi = 0;
        #pragma unroll
        for (int jj = 0; jj < 16; ++jj) {
            float v = sc[base + jj];
            if (v > bv) { bv = v; bi = base + jj; }   // asc order -> low idx tie
        }
        #pragma unroll
        for (int off = 16; off > 0; off >>= 1) {
            float ov = __shfl_down_sync(0xffffffffu, bv, off);
            int   oi = __shfl_down_sync(0xffffffffu, bi, off);
            if (ov > bv || (ov == bv && oi < bi)) { bv = ov; bi = oi; }
        }
        if ((tid & 31) == 0) { red_v[tid >> 5] = bv; red_i[tid >> 5] = bi; }
        __syncthreads();
        if (lt == 0) {
            float v0 = red_v[sid * 2]; int i0 = red_i[sid * 2];
            float v1 = red_v[sid * 2 + 1]; int i1 = red_i[sid * 2 + 1];
            if (v1 > v0 || (v1 == v0 && i1 < i0)) { v0 = v1; i0 = i1; }
            s_tv[sid][p] = v0; s_ti[sid][p] = i0;
            sc[i0] = -3.4e38f;
        }
        __syncthreads();
    }

    // softmax over the 13 selected values (per series)
    if (lt == 0) {
        float mx = s_tv[sid][0];
        float e[KTOP], sum = 0.f;
        #pragma unroll
        for (int p = 0; p < KTOP; ++p) { e[p] = expf(s_tv[sid][p] - mx); sum += e[p]; }
        float inv = 1.0f / sum;
        #pragma unroll
        for (int p = 0; p < KTOP; ++p) s_w[sid][p] = e[p] * inv;
    }
    __syncthreads();

    // agg[l] = sum_k w_k * v[(l + idx_k) & 1023]
    const float* sv = fbf + 6144 + (sid << 10);
    float* aggrow = g_agg + offA + (size_t)sid * NL;
    float wgt[KTOP]; int ix[KTOP];
    #pragma unroll
    for (int p = 0; p < KTOP; ++p) { wgt[p] = s_w[sid][p]; ix[p] = s_ti[sid][p]; }
    #pragma unroll
    for (int jj = 0; jj < 16; ++jj) {
        int l = lt + jj * 64;
        float acc = 0.f;
        #pragma unroll
        for (int p = 0; p < KTOP; ++p)
            acc += wgt[p] * sv[(l + ix[p]) & 1023];
        aggrow[l] = acc;
    }
}

// ---------------------------------------------------------------------------
// Kernel 3: transpose-broadcast agg[b][d][l] -> out[b][l][h*64+d], h=0..7
// ---------------------------------------------------------------------------
__global__ __launch_bounds__(256) void out_kernel(float* __restrict__ out)
{
    __shared__ float t[64][33];
    const int b   = blockIdx.y;
    const int l0  = blockIdx.x * 32;
    const int tid = threadIdx.x;
    const float* agg = g_agg + (size_t)b * NDH * NL;

    #pragma unroll
    for (int i = 0; i < 8; ++i) {
        int flat = tid + i * 256;
        int dd   = flat >> 5;
        int ll   = flat & 31;
        t[dd][ll] = agg[(size_t)dd * NL + l0 + ll];
    }
    __syncthreads();

    float* obase = out + ((size_t)b * NL + l0) * (NDH * 8);
    #pragma unroll
    for (int i = 0; i < 16; ++i) {
        int f4  = tid + i * 256;
        int ll  = f4 >> 7;
        int c0  = (f4 & 127) * 4;
        int cc  = c0 & 63;
        float4 v = make_float4(t[cc][ll], t[cc + 1][ll], t[cc + 2][ll], t[cc + 3][ll]);
        *reinterpret_cast<float4*>(obase + (size_t)ll * 512 + c0) = v;
    }
}

// ---------------------------------------------------------------------------
extern "C" void kernel_launch(void* const* d_in, const int* in_sizes, int n_in,
                              void* d_out, int out_size)
{
    const float* Q  = (const float*)d_in[0];
    const float* K  = (const float*)d_in[1];
    const float* V  = (const float*)d_in[2];
    const float* Wq = (const float*)d_in[3];
    const float* bq = (const float*)d_in[4];
    float* out = (float*)d_out;

    proj_kernel<<<dim3(NL / 128, NB, 3), 256>>>(Q, K, V, Wq, bq);
    corr_kernel<<<dim3(NDH / 2, NB), 128>>>();
    out_kernel<<<dim3(NL / 32, NB), 256>>>(out);
}